// round 5
// baseline (speedup 1.0000x reference)
#include <cuda_runtime.h>
#include <cuda_bf16.h>
#include <math.h>

#define N 4096
#define G (3 * N)
#define CCHUNK 16          // rows per colmv block -> grid (4, 256) = 1024 blocks

// ---------------- device scratch ----------------
__device__ float g_t[N];        // logits buffer
__device__ float g_vec[N];      // softmax output
__device__ float g_sk[N];       // GRU hidden state
__device__ float g_u[N];        // u = W2 @ sk
__device__ float g_xk[N];       // x_k
__device__ float g_gi[G];       // w_ih @ xk
__device__ float g_gh[G];       // w_hh @ sk
__device__ float g_Pr[3];       // accumulated probabilities

// bf16 copies of the GRU weights (static device arrays: no runtime allocation)
__device__ __nv_bfloat16 g_wih_bf[(size_t)G * N];   // 96 MB
__device__ __nv_bfloat16 g_whh_bf[(size_t)G * N];   // 96 MB

// ---------------- kernels ----------------

__global__ void init_kernel() {
    int i = blockIdx.x * blockDim.x + threadIdx.x;
    if (i < N) g_t[i] = 0.0f;
    if (i < 3) g_Pr[i] = 0.0f;
}

// fp32 -> bf16 conversion, 8 elements per thread (read 2x float4, write 1x uint4)
__global__ void convert_bf16_kernel(const float* __restrict__ src,
                                    __nv_bfloat16* __restrict__ dst,
                                    int n8) {
    int idx = blockIdx.x * blockDim.x + threadIdx.x;
    if (idx >= n8) return;
    const float4* s4 = (const float4*)src;
    float4 a = __ldg(&s4[2 * idx]);
    float4 b = __ldg(&s4[2 * idx + 1]);
    __nv_bfloat162 p0 = __floats2bfloat162_rn(a.x, a.y);
    __nv_bfloat162 p1 = __floats2bfloat162_rn(a.z, a.w);
    __nv_bfloat162 p2 = __floats2bfloat162_rn(b.x, b.y);
    __nv_bfloat162 p3 = __floats2bfloat162_rn(b.z, b.w);
    uint4 out;
    out.x = *(unsigned int*)&p0;
    out.y = *(unsigned int*)&p1;
    out.z = *(unsigned int*)&p2;
    out.w = *(unsigned int*)&p3;
    ((uint4*)dst)[idx] = out;
}

// y[j] += sum_r x[r] * A[r, j]; float4 columns, CHUNK=16 rows per block.
// grid: (N/1024, N/CCHUNK) = (4, 256), block: 256
__global__ void colmv_kernel(const float* __restrict__ A,
                             const float* __restrict__ x,
                             float* __restrict__ y,
                             int step, const int* __restrict__ Kp) {
    if (step >= *Kp) return;
    __shared__ float xs[CCHUNK];
    int j4 = blockIdx.x * blockDim.x + threadIdx.x;
    int r0 = blockIdx.y * CCHUNK;
    if (threadIdx.x < CCHUNK) xs[threadIdx.x] = x[r0 + threadIdx.x];
    __syncthreads();
    const float4* A4 = (const float4*)A;
    float4 acc = make_float4(0.f, 0.f, 0.f, 0.f);
#pragma unroll
    for (int r = 0; r < CCHUNK; r++) {
        float4 a = __ldg(&A4[(size_t)(r0 + r) * (N / 4) + j4]);
        float s = xs[r];
        acc.x += s * a.x; acc.y += s * a.y; acc.z += s * a.z; acc.w += s * a.w;
    }
    float* yp = y + j4 * 4;
    atomicAdd(yp + 0, acc.x);
    atomicAdd(yp + 1, acc.y);
    atomicAdd(yp + 2, acc.z);
    atomicAdd(yp + 3, acc.w);
}

// fp32 rowmv: y[row] = dot(A[row], x); optionally zero t[row].
// grid: rows, block: 128
__global__ void rowmv_kernel(const float* __restrict__ A,
                             const float* __restrict__ x,
                             float* __restrict__ y,
                             float* t_zero,
                             int step, const int* __restrict__ Kp) {
    if (step >= *Kp) return;
    int row = blockIdx.x;
    if (t_zero != nullptr && threadIdx.x == 0) t_zero[row] = 0.0f;
    const float4* A4 = (const float4*)(A + (size_t)row * N);
    const float4* x4 = (const float4*)x;
    float acc = 0.0f;
#pragma unroll 8
    for (int i = threadIdx.x; i < N / 4; i += 128) {
        float4 a = __ldg(&A4[i]);
        float4 b = __ldg(&x4[i]);
        acc += a.x * b.x + a.y * b.y + a.z * b.z + a.w * b.w;
    }
#pragma unroll
    for (int o = 16; o; o >>= 1) acc += __shfl_down_sync(0xffffffffu, acc, o);
    __shared__ float sh[4];
    if ((threadIdx.x & 31) == 0) sh[threadIdx.x >> 5] = acc;
    __syncthreads();
    if (threadIdx.x == 0) y[row] = sh[0] + sh[1] + sh[2] + sh[3];
}

// Fused GRU gate matvecs on bf16 weights, fp32 x, fp32 accumulate.
// rows [0,G): gi = w_ih @ xk ; rows [G, 2G): gh = w_hh @ sk
// grid: 2*G, block: 128
__global__ void gates_bf16_kernel(int step, const int* __restrict__ Kp) {
    if (step >= *Kp) return;
    int row = blockIdx.x;
    const __nv_bfloat16* Arow;
    const float* x;
    float* ydst;
    if (row < G) {
        Arow = g_wih_bf + (size_t)row * N;
        x = g_xk;
        ydst = g_gi + row;
    } else {
        Arow = g_whh_bf + (size_t)(row - G) * N;
        x = g_sk;
        ydst = g_gh + (row - G);
    }
    const uint4* A8 = (const uint4*)Arow;         // 8 bf16 per uint4
    const float4* x4 = (const float4*)x;
    float acc = 0.0f;
#pragma unroll 4
    for (int i = threadIdx.x; i < N / 8; i += 128) {
        uint4 w = __ldg(&A8[i]);
        float4 x0 = __ldg(&x4[2 * i]);
        float4 x1 = __ldg(&x4[2 * i + 1]);
        float2 f0 = __bfloat1622float2(*(__nv_bfloat162*)&w.x);
        float2 f1 = __bfloat1622float2(*(__nv_bfloat162*)&w.y);
        float2 f2 = __bfloat1622float2(*(__nv_bfloat162*)&w.z);
        float2 f3 = __bfloat1622float2(*(__nv_bfloat162*)&w.w);
        acc += f0.x * x0.x + f0.y * x0.y + f1.x * x0.z + f1.y * x0.w;
        acc += f2.x * x1.x + f2.y * x1.y + f3.x * x1.z + f3.y * x1.w;
    }
#pragma unroll
    for (int o = 16; o; o >>= 1) acc += __shfl_down_sync(0xffffffffu, acc, o);
    __shared__ float sh[4];
    if ((threadIdx.x & 31) == 0) sh[threadIdx.x >> 5] = acc;
    __syncthreads();
    if (threadIdx.x == 0) *ydst = sh[0] + sh[1] + sh[2] + sh[3];
}

// out = softmax(t) over N; zeroes z1[0:n1]. single block 1024 threads
__global__ void softmax_kernel(const float* __restrict__ t,
                               float* __restrict__ out,
                               float* z1, int n1,
                               int step, const int* __restrict__ Kp) {
    if (step >= *Kp) return;
    int tid = threadIdx.x;
    __shared__ float red[32];

    float m = -INFINITY;
    for (int i = tid; i < N; i += 1024) m = fmaxf(m, t[i]);
#pragma unroll
    for (int o = 16; o; o >>= 1) m = fmaxf(m, __shfl_down_sync(0xffffffffu, m, o));
    if ((tid & 31) == 0) red[tid >> 5] = m;
    __syncthreads();
    if (tid < 32) {
        float v = red[tid];
#pragma unroll
        for (int o = 16; o; o >>= 1) v = fmaxf(v, __shfl_down_sync(0xffffffffu, v, o));
        if (tid == 0) red[0] = v;
    }
    __syncthreads();
    float M = red[0];
    __syncthreads();

    float s = 0.0f;
    for (int i = tid; i < N; i += 1024) {
        float e = expf(t[i] - M);
        out[i] = e;
        s += e;
    }
#pragma unroll
    for (int o = 16; o; o >>= 1) s += __shfl_down_sync(0xffffffffu, s, o);
    if ((tid & 31) == 0) red[tid >> 5] = s;
    __syncthreads();
    if (tid < 32) {
        float v = red[tid];
#pragma unroll
        for (int o = 16; o; o >>= 1) v += __shfl_down_sync(0xffffffffu, v, o);
        if (tid == 0) red[0] = v;
    }
    __syncthreads();
    float inv = 1.0f / red[0];
    for (int i = tid; i < N; i += 1024) out[i] *= inv;

    if (z1) for (int i = tid; i < n1; i += 1024) z1[i] = 0.0f;
}

// Fused GRU elementwise + W3 feature dot + 3-label softmax accumulation.
__global__ void gru_accum_kernel(const float* __restrict__ W3,
                                 int step, const int* __restrict__ Kp) {
    if (step >= *Kp) return;
    int tid = threadIdx.x;
    float l0 = 0.0f, l1 = 0.0f, l2 = 0.0f;

    for (int i = tid; i < N; i += 1024) {
        float h = g_sk[i];
        float x = g_xk[i];
        float ir = g_gi[i],         hr = g_gh[i];
        float iz = g_gi[N + i],     hz = g_gh[N + i];
        float in = g_gi[2 * N + i], hn = g_gh[2 * N + i];
        float r = 1.0f / (1.0f + expf(-(ir + hr)));
        float z = 1.0f / (1.0f + expf(-(iz + hz)));
        float nn = tanhf(in + r * hn);
        float hnew = (1.0f - z) * nn + z * h;
        g_sk[i] = hnew;

        float ad = fabsf(hnew - x);
        float pr = hnew * x;
        const float* w0 = W3 + (size_t)i * 3;
        const float* w1 = W3 + (size_t)(N + i) * 3;
        const float* w2 = W3 + (size_t)(2 * N + i) * 3;
        const float* w3 = W3 + (size_t)(3 * N + i) * 3;
        l0 += w0[0] * hnew + w1[0] * x + w2[0] * ad + w3[0] * pr;
        l1 += w0[1] * hnew + w1[1] * x + w2[1] * ad + w3[1] * pr;
        l2 += w0[2] * hnew + w1[2] * x + w2[2] * ad + w3[2] * pr;
    }
#pragma unroll
    for (int o = 16; o; o >>= 1) {
        l0 += __shfl_down_sync(0xffffffffu, l0, o);
        l1 += __shfl_down_sync(0xffffffffu, l1, o);
        l2 += __shfl_down_sync(0xffffffffu, l2, o);
    }
    __shared__ float s0[32], s1[32], s2[32];
    if ((tid & 31) == 0) {
        s0[tid >> 5] = l0; s1[tid >> 5] = l1; s2[tid >> 5] = l2;
    }
    __syncthreads();
    if (tid == 0) {
        float a = 0.f, b = 0.f, c = 0.f;
#pragma unroll
        for (int w = 0; w < 32; w++) { a += s0[w]; b += s1[w]; c += s2[w]; }
        float m = fmaxf(a, fmaxf(b, c));
        float ea = expf(a - m), eb = expf(b - m), ec = expf(c - m);
        float s = ea + eb + ec;
        g_Pr[0] += ea / s;
        g_Pr[1] += eb / s;
        g_Pr[2] += ec / s;
    }
}

__global__ void final_kernel(float* __restrict__ out, const int* __restrict__ Kp) {
    int i = threadIdx.x;
    if (i < 3) out[i] = g_Pr[i] / (float)(*Kp);
}

// ---------------- host launch ----------------
extern "C" void kernel_launch(void* const* d_in, const int* in_sizes, int n_in,
                              void* d_out, int out_size) {
    const float* M_h   = (const float*)d_in[0];
    const float* M_p   = (const float*)d_in[1];
    const float* w1    = (const float*)d_in[2];
    const float* W2    = (const float*)d_in[3];
    const float* W3    = (const float*)d_in[4];
    const float* w_ih  = (const float*)d_in[5];
    const float* w_hh  = (const float*)d_in[6];
    const int*   Kp    = (const int*)d_in[7];
    float* out = (float*)d_out;

    float *t, *vec, *sk, *u, *xk;
    __nv_bfloat16 *wih_bf, *whh_bf;
    cudaGetSymbolAddress((void**)&t,      g_t);
    cudaGetSymbolAddress((void**)&vec,    g_vec);
    cudaGetSymbolAddress((void**)&sk,     g_sk);
    cudaGetSymbolAddress((void**)&u,      g_u);
    cudaGetSymbolAddress((void**)&xk,     g_xk);
    cudaGetSymbolAddress((void**)&wih_bf, g_wih_bf);
    cudaGetSymbolAddress((void**)&whh_bf, g_whh_bf);

    dim3 cgrid(N / 1024, N / CCHUNK);   // (4, 256) = 1024 blocks

    // weight conversion (deterministic, every call)
    const int n8 = G * (N / 8);   // 6,291,456 uint4-groups per matrix
    convert_bf16_kernel<<<(n8 + 255) / 256, 256>>>(w_ih, wih_bf, n8);
    convert_bf16_kernel<<<(n8 + 255) / 256, 256>>>(w_hh, whh_bf, n8);

    // prologue: alpha = softmax(w1^T M_h); sk0 = alpha @ M_h
    init_kernel<<<(N + 1023) / 1024, 1024>>>();
    colmv_kernel<<<cgrid, 256>>>(M_h, w1, t, 0, Kp);
    softmax_kernel<<<1, 1024>>>(t, vec, sk, N, 0, Kp);
    colmv_kernel<<<cgrid, 256>>>(M_h, vec, sk, 0, Kp);

    const int MAX_STEPS = 8;
    for (int s = 0; s < MAX_STEPS; s++) {
        // u = W2 @ sk ; zero t
        rowmv_kernel<<<N, 128>>>(W2, sk, u, t, s, Kp);
        // logits = u^T @ M_p
        colmv_kernel<<<cgrid, 256>>>(M_p, u, t, s, Kp);
        // beta = softmax(logits); zero xk
        softmax_kernel<<<1, 1024>>>(t, vec, xk, N, s, Kp);
        // xk = beta^T @ M_p
        colmv_kernel<<<cgrid, 256>>>(M_p, vec, xk, s, Kp);
        // gi = w_ih @ xk ; gh = w_hh @ sk (bf16 weights)
        gates_bf16_kernel<<<2 * G, 128>>>(s, Kp);
        // GRU + feature dot + label softmax accumulation
        gru_accum_kernel<<<1, 1024>>>(W3, s, Kp);
    }

    final_kernel<<<1, 32>>>(out, Kp);
}

// round 6
// speedup vs baseline: 1.1868x; 1.1868x over previous
#include <cuda_runtime.h>
#include <cuda_bf16.h>
#include <math.h>

#define N 4096
#define G (3 * N)
#define CCHUNK 64          // rows per colmv block (proven R1 config)

// ---------------- device scratch ----------------
__device__ float g_t[N];        // logits buffer
__device__ float g_vec[N];      // softmax output
__device__ float g_sk[N];       // GRU hidden state
__device__ float g_u[N];        // u = W2 @ sk
__device__ float g_xk[N];       // x_k
__device__ float g_gi[G];       // w_ih @ xk
__device__ float g_gh[G];       // w_hh @ sk
__device__ float g_Pr[3];       // accumulated probabilities

// bf16 copies of the GRU weights (static device arrays: no runtime allocation)
__device__ __nv_bfloat16 g_wih_bf[(size_t)G * N];   // 96 MB
__device__ __nv_bfloat16 g_whh_bf[(size_t)G * N];   // 96 MB

// ---------------- kernels ----------------

__global__ void init_kernel() {
    int i = blockIdx.x * blockDim.x + threadIdx.x;
    if (i < N) g_t[i] = 0.0f;
    if (i < 3) g_Pr[i] = 0.0f;
}

// fp32 -> bf16 conversion, 8 elements per thread
__global__ void convert_bf16_kernel(const float* __restrict__ src,
                                    __nv_bfloat16* __restrict__ dst,
                                    int n8) {
    int idx = blockIdx.x * blockDim.x + threadIdx.x;
    if (idx >= n8) return;
    const float4* s4 = (const float4*)src;
    float4 a = __ldg(&s4[2 * idx]);
    float4 b = __ldg(&s4[2 * idx + 1]);
    __nv_bfloat162 p0 = __floats2bfloat162_rn(a.x, a.y);
    __nv_bfloat162 p1 = __floats2bfloat162_rn(a.z, a.w);
    __nv_bfloat162 p2 = __floats2bfloat162_rn(b.x, b.y);
    __nv_bfloat162 p3 = __floats2bfloat162_rn(b.z, b.w);
    uint4 out;
    out.x = *(unsigned int*)&p0;
    out.y = *(unsigned int*)&p1;
    out.z = *(unsigned int*)&p2;
    out.w = *(unsigned int*)&p3;
    ((uint4*)dst)[idx] = out;
}

// y[j] += sum_r x[r] * A[r, j]  (proven R1 config: scalar loads, CHUNK=64)
// grid: (N/256, N/CCHUNK) = (16, 64) = 1024 blocks, block: 256
__global__ void colmv_kernel(const float* __restrict__ A,
                             const float* __restrict__ x,
                             float* __restrict__ y,
                             int step, const int* __restrict__ Kp) {
    if (step >= *Kp) return;
    __shared__ float xs[CCHUNK];
    int j = blockIdx.x * blockDim.x + threadIdx.x;
    int r0 = blockIdx.y * CCHUNK;
    if (threadIdx.x < CCHUNK) xs[threadIdx.x] = x[r0 + threadIdx.x];
    __syncthreads();
    const float* Ap = A + (size_t)r0 * N + j;
    float acc = 0.0f;
#pragma unroll 8
    for (int r = 0; r < CCHUNK; r++)
        acc += xs[r] * Ap[(size_t)r * N];
    atomicAdd(&y[j], acc);
}

// fp32 rowmv: y[row] = dot(A[row], x); optionally zero t[row].
// grid: rows, block: 128
__global__ void rowmv_kernel(const float* __restrict__ A,
                             const float* __restrict__ x,
                             float* __restrict__ y,
                             float* t_zero,
                             int step, const int* __restrict__ Kp) {
    if (step >= *Kp) return;
    int row = blockIdx.x;
    if (t_zero != nullptr && threadIdx.x == 0) t_zero[row] = 0.0f;
    const float4* A4 = (const float4*)(A + (size_t)row * N);
    const float4* x4 = (const float4*)x;
    float acc = 0.0f;
#pragma unroll 8
    for (int i = threadIdx.x; i < N / 4; i += 128) {
        float4 a = __ldg(&A4[i]);
        float4 b = __ldg(&x4[i]);
        acc += a.x * b.x + a.y * b.y + a.z * b.z + a.w * b.w;
    }
#pragma unroll
    for (int o = 16; o; o >>= 1) acc += __shfl_down_sync(0xffffffffu, acc, o);
    __shared__ float sh[4];
    if ((threadIdx.x & 31) == 0) sh[threadIdx.x >> 5] = acc;
    __syncthreads();
    if (threadIdx.x == 0) y[row] = sh[0] + sh[1] + sh[2] + sh[3];
}

// Fused GRU gate matvecs on bf16 weights, fp32 x, fp32 accumulate.
// rows [0,G): gi = w_ih @ xk ; rows [G, 2G): gh = w_hh @ sk
// grid: 2*G, block: 128
__global__ void gates_bf16_kernel(int step, const int* __restrict__ Kp) {
    if (step >= *Kp) return;
    int row = blockIdx.x;
    const __nv_bfloat16* Arow;
    const float* x;
    float* ydst;
    if (row < G) {
        Arow = g_wih_bf + (size_t)row * N;
        x = g_xk;
        ydst = g_gi + row;
    } else {
        Arow = g_whh_bf + (size_t)(row - G) * N;
        x = g_sk;
        ydst = g_gh + (row - G);
    }
    const uint4* A8 = (const uint4*)Arow;         // 8 bf16 per uint4
    const float4* x4 = (const float4*)x;
    float acc = 0.0f;
#pragma unroll 4
    for (int i = threadIdx.x; i < N / 8; i += 128) {
        uint4 w = __ldg(&A8[i]);
        float4 x0 = __ldg(&x4[2 * i]);
        float4 x1 = __ldg(&x4[2 * i + 1]);
        float2 f0 = __bfloat1622float2(*(__nv_bfloat162*)&w.x);
        float2 f1 = __bfloat1622float2(*(__nv_bfloat162*)&w.y);
        float2 f2 = __bfloat1622float2(*(__nv_bfloat162*)&w.z);
        float2 f3 = __bfloat1622float2(*(__nv_bfloat162*)&w.w);
        acc += f0.x * x0.x + f0.y * x0.y + f1.x * x0.z + f1.y * x0.w;
        acc += f2.x * x1.x + f2.y * x1.y + f3.x * x1.z + f3.y * x1.w;
    }
#pragma unroll
    for (int o = 16; o; o >>= 1) acc += __shfl_down_sync(0xffffffffu, acc, o);
    __shared__ float sh[4];
    if ((threadIdx.x & 31) == 0) sh[threadIdx.x >> 5] = acc;
    __syncthreads();
    if (threadIdx.x == 0) *ydst = sh[0] + sh[1] + sh[2] + sh[3];
}

// out = softmax(t) over N; zeroes z1[0:n1]. single block 1024 threads
__global__ void softmax_kernel(const float* __restrict__ t,
                               float* __restrict__ out,
                               float* z1, int n1,
                               int step, const int* __restrict__ Kp) {
    if (step >= *Kp) return;
    int tid = threadIdx.x;
    __shared__ float red[32];

    float m = -INFINITY;
    for (int i = tid; i < N; i += 1024) m = fmaxf(m, t[i]);
#pragma unroll
    for (int o = 16; o; o >>= 1) m = fmaxf(m, __shfl_down_sync(0xffffffffu, m, o));
    if ((tid & 31) == 0) red[tid >> 5] = m;
    __syncthreads();
    if (tid < 32) {
        float v = red[tid];
#pragma unroll
        for (int o = 16; o; o >>= 1) v = fmaxf(v, __shfl_down_sync(0xffffffffu, v, o));
        if (tid == 0) red[0] = v;
    }
    __syncthreads();
    float M = red[0];
    __syncthreads();

    float s = 0.0f;
    for (int i = tid; i < N; i += 1024) {
        float e = expf(t[i] - M);
        out[i] = e;
        s += e;
    }
#pragma unroll
    for (int o = 16; o; o >>= 1) s += __shfl_down_sync(0xffffffffu, s, o);
    if ((tid & 31) == 0) red[tid >> 5] = s;
    __syncthreads();
    if (tid < 32) {
        float v = red[tid];
#pragma unroll
        for (int o = 16; o; o >>= 1) v += __shfl_down_sync(0xffffffffu, v, o);
        if (tid == 0) red[0] = v;
    }
    __syncthreads();
    float inv = 1.0f / red[0];
    for (int i = tid; i < N; i += 1024) out[i] *= inv;

    if (z1) for (int i = tid; i < n1; i += 1024) z1[i] = 0.0f;
}

// Fused GRU elementwise + W3 feature dot + 3-label softmax accumulation.
__global__ void gru_accum_kernel(const float* __restrict__ W3,
                                 int step, const int* __restrict__ Kp) {
    if (step >= *Kp) return;
    int tid = threadIdx.x;
    float l0 = 0.0f, l1 = 0.0f, l2 = 0.0f;

    for (int i = tid; i < N; i += 1024) {
        float h = g_sk[i];
        float x = g_xk[i];
        float ir = g_gi[i],         hr = g_gh[i];
        float iz = g_gi[N + i],     hz = g_gh[N + i];
        float in = g_gi[2 * N + i], hn = g_gh[2 * N + i];
        float r = 1.0f / (1.0f + expf(-(ir + hr)));
        float z = 1.0f / (1.0f + expf(-(iz + hz)));
        float nn = tanhf(in + r * hn);
        float hnew = (1.0f - z) * nn + z * h;
        g_sk[i] = hnew;

        float ad = fabsf(hnew - x);
        float pr = hnew * x;
        const float* w0 = W3 + (size_t)i * 3;
        const float* w1 = W3 + (size_t)(N + i) * 3;
        const float* w2 = W3 + (size_t)(2 * N + i) * 3;
        const float* w3 = W3 + (size_t)(3 * N + i) * 3;
        l0 += w0[0] * hnew + w1[0] * x + w2[0] * ad + w3[0] * pr;
        l1 += w0[1] * hnew + w1[1] * x + w2[1] * ad + w3[1] * pr;
        l2 += w0[2] * hnew + w1[2] * x + w2[2] * ad + w3[2] * pr;
    }
#pragma unroll
    for (int o = 16; o; o >>= 1) {
        l0 += __shfl_down_sync(0xffffffffu, l0, o);
        l1 += __shfl_down_sync(0xffffffffu, l1, o);
        l2 += __shfl_down_sync(0xffffffffu, l2, o);
    }
    __shared__ float s0[32], s1[32], s2[32];
    if ((tid & 31) == 0) {
        s0[tid >> 5] = l0; s1[tid >> 5] = l1; s2[tid >> 5] = l2;
    }
    __syncthreads();
    if (tid == 0) {
        float a = 0.f, b = 0.f, c = 0.f;
#pragma unroll
        for (int w = 0; w < 32; w++) { a += s0[w]; b += s1[w]; c += s2[w]; }
        float m = fmaxf(a, fmaxf(b, c));
        float ea = expf(a - m), eb = expf(b - m), ec = expf(c - m);
        float s = ea + eb + ec;
        g_Pr[0] += ea / s;
        g_Pr[1] += eb / s;
        g_Pr[2] += ec / s;
    }
}

__global__ void final_kernel(float* __restrict__ out, const int* __restrict__ Kp) {
    int i = threadIdx.x;
    if (i < 3) out[i] = g_Pr[i] / (float)(*Kp);
}

// ---------------- host launch ----------------
extern "C" void kernel_launch(void* const* d_in, const int* in_sizes, int n_in,
                              void* d_out, int out_size) {
    const float* M_h   = (const float*)d_in[0];
    const float* M_p   = (const float*)d_in[1];
    const float* w1    = (const float*)d_in[2];
    const float* W2    = (const float*)d_in[3];
    const float* W3    = (const float*)d_in[4];
    const float* w_ih  = (const float*)d_in[5];
    const float* w_hh  = (const float*)d_in[6];
    const int*   Kp    = (const int*)d_in[7];
    float* out = (float*)d_out;

    float *t, *vec, *sk, *u, *xk;
    __nv_bfloat16 *wih_bf, *whh_bf;
    cudaGetSymbolAddress((void**)&t,      g_t);
    cudaGetSymbolAddress((void**)&vec,    g_vec);
    cudaGetSymbolAddress((void**)&sk,     g_sk);
    cudaGetSymbolAddress((void**)&u,      g_u);
    cudaGetSymbolAddress((void**)&xk,     g_xk);
    cudaGetSymbolAddress((void**)&wih_bf, g_wih_bf);
    cudaGetSymbolAddress((void**)&whh_bf, g_whh_bf);

    dim3 cgrid(N / 256, N / CCHUNK);   // (16, 64) = 1024 blocks

    // weight conversion (deterministic, every call)
    const int n8 = G * (N / 8);
    convert_bf16_kernel<<<(n8 + 255) / 256, 256>>>(w_ih, wih_bf, n8);
    convert_bf16_kernel<<<(n8 + 255) / 256, 256>>>(w_hh, whh_bf, n8);

    // prologue: alpha = softmax(w1^T M_h); sk0 = alpha @ M_h
    init_kernel<<<(N + 1023) / 1024, 1024>>>();
    colmv_kernel<<<cgrid, 256>>>(M_h, w1, t, 0, Kp);
    softmax_kernel<<<1, 1024>>>(t, vec, sk, N, 0, Kp);
    colmv_kernel<<<cgrid, 256>>>(M_h, vec, sk, 0, Kp);

    const int MAX_STEPS = 8;
    for (int s = 0; s < MAX_STEPS; s++) {
        // u = W2 @ sk ; zero t
        rowmv_kernel<<<N, 128>>>(W2, sk, u, t, s, Kp);
        // logits = u^T @ M_p
        colmv_kernel<<<cgrid, 256>>>(M_p, u, t, s, Kp);
        // beta = softmax(logits); zero xk
        softmax_kernel<<<1, 1024>>>(t, vec, xk, N, s, Kp);
        // xk = beta^T @ M_p
        colmv_kernel<<<cgrid, 256>>>(M_p, vec, xk, s, Kp);
        // gi = w_ih @ xk ; gh = w_hh @ sk (bf16 weights)
        gates_bf16_kernel<<<2 * G, 128>>>(s, Kp);
        // GRU + feature dot + label softmax accumulation
        gru_accum_kernel<<<1, 1024>>>(W3, s, Kp);
    }

    final_kernel<<<1, 32>>>(out, Kp);
}